// round 14
// baseline (speedup 1.0000x reference)
#include <cuda_runtime.h>
#include <cuda_bf16.h>
#include <cstdint>

#define Nn 100000
#define Hh 96

typedef unsigned long long u64;

// ---------------- static device scratch (no allocations allowed) ----------------
// Invariant: g_accum (agg + den) is ZERO at kernel_launch entry; combine re-zeroes
// after consuming, so graph replays see the same state every time.
__device__ __align__(16) float g_accum[3*Nn*Hh + 3*Nn];  // agg0,agg1,agg2 then den0,den1,den2
__device__ __align__(16) float g_A[4*Nn];                // aS0, aD0, aS1, aD1
__device__ __align__(16) float g_Mbig[384*Hh];           // rows 0-95: M0, then M1_t (t=0..2)
__device__ __align__(16) float g_D[3][Hh*Hh];            // WmDst_t @ Wu_t
__device__ __align__(16) float g_V[4*Hh];                // attention vectors
__device__ __align__(16) float g_cw[3][Hh];              // c_t @ Wu_t
__device__ __align__(16) float g_bu2[Hh];                // bu + sum cw
__device__ __align__(16) __nv_bfloat16 g_MbT_hi[Hh*384]; // B^T split: [j][k]
__device__ __align__(16) __nv_bfloat16 g_MbT_lo[Hh*384];

// ---------------- prep: M1_t, D_t, M0, V vectors, cw, bu2 ----------------
#define PREP_ITEMS  (3*Hh*Hh + Hh*Hh + 2*Hh)
#define PREP_BLOCKS ((PREP_ITEMS + 255)/256)

__global__ void k_prep(
    const float* __restrict__ Wn0, const float* __restrict__ Wa0,
    const float* __restrict__ Wn1, const float* __restrict__ Wa1,
    const float* __restrict__ Wm0, const float* __restrict__ bm0, const float* __restrict__ ef0,
    const float* __restrict__ Wm1, const float* __restrict__ bm1, const float* __restrict__ ef1,
    const float* __restrict__ Wm2, const float* __restrict__ bm2, const float* __restrict__ ef2,
    const float* __restrict__ Wu, const float* __restrict__ bu)
{
    const int NA = 3*Hh*Hh;
    const int NB = Hh*Hh;
    int idx = blockIdx.x*blockDim.x + threadIdx.x;
    const float* Wms[3] = {Wm0, Wm1, Wm2};
    const float* bms[3] = {bm0, bm1, bm2};
    const float* efs[3] = {ef0, ef1, ef2};

    if (idx < NA) {
        int t = idx / (Hh*Hh);
        int r = idx % (Hh*Hh);
        int k = r / Hh, j = r % Hh;
        const float* Wm = Wms[t];
        float m1 = 0.f, dd = 0.f;
        const float* wuBase = Wu + (Hh + t*Hh)*Hh + j;
        for (int c = 0; c < Hh; c++) {
            float wu = wuBase[c*Hh];
            m1 += Wm[k*Hh + c] * wu;
            dd += Wm[(Hh + k)*Hh + c] * wu;
        }
        g_Mbig[(Hh + t*Hh + k)*Hh + j] = m1;
        g_D[t][k*Hh + j] = dd;
    } else if (idx < NA + NB) {
        int r = idx - NA;
        int k = r / Hh, j = r % Hh;
        float m0 = Wu[k*Hh + j];
        #pragma unroll
        for (int t = 0; t < 3; t++) {
            const float* Wm = Wms[t];
            const float* wuBase = Wu + (Hh + t*Hh)*Hh + j;
            for (int c = 0; c < Hh; c++)
                m0 += Wm[(Hh + k)*Hh + c] * wuBase[c*Hh];
        }
        g_Mbig[k*Hh + j] = m0;
    } else if (idx < NA + NB + Hh) {
        int i = idx - NA - NB;
        float s0 = 0.f, d0 = 0.f, s1 = 0.f, d1 = 0.f;
        for (int j = 0; j < 32; j++) {
            float w0 = Wn0[i*32+j], w1 = Wn1[i*32+j];
            s0 += w0*Wa0[j];     d0 += w0*Wa0[32+j];
            s1 += w1*Wa1[j];     d1 += w1*Wa1[32+j];
        }
        g_V[0*Hh+i] = s0; g_V[1*Hh+i] = d0; g_V[2*Hh+i] = s1; g_V[3*Hh+i] = d1;
    } else if (idx < NA + NB + 2*Hh) {
        int i = idx - NA - NB - Hh;
        float b = bu[i];
        #pragma unroll
        for (int t = 0; t < 3; t++) {
            float cw = 0.f;
            for (int c = 0; c < Hh; c++) {
                float ct = bms[t][c];
                for (int d = 0; d < 16; d++) ct += efs[t][d] * Wms[t][(192+d)*Hh + c];
                cw += ct * Wu[(Hh + t*Hh + c)*Hh + i];
            }
            g_cw[t][i] = cw;
            b += cw;
        }
        g_bu2[i] = b;
    }
}

// ---------------- anode + B-transpose/split fused ----------------
#define ANODE_BLOCKS (((Nn + 3)/4*32 + 255)/256)
#define BT_BLOCKS    ((Hh*384 + 255)/256)

__global__ void k_anode_bt(const float* __restrict__ h) {
    if (blockIdx.x >= ANODE_BLOCKS) {
        int idx = (blockIdx.x - ANODE_BLOCKS)*blockDim.x + threadIdx.x;
        if (idx >= Hh*384) return;
        int j = idx / 384, k = idx % 384;
        float v = g_Mbig[k*Hh + j];
        __nv_bfloat16 hi = __float2bfloat16_rn(v);
        __nv_bfloat16 lo = __float2bfloat16_rn(v - __bfloat162float(hi));
        g_MbT_hi[idx] = hi;
        g_MbT_lo[idx] = lo;
        return;
    }
    __shared__ float sv[4*Hh];
    for (int i = threadIdx.x; i < 4*Hh; i += blockDim.x) sv[i] = g_V[i];
    __syncthreads();
    int gtid = blockIdx.x*blockDim.x + threadIdx.x;
    int lane = gtid & 31;
    int k = lane & 7;
    int n = (gtid >> 5)*4 + (lane >> 3);
    if (n >= Nn) return;
    const float4* hp = reinterpret_cast<const float4*>(h + (size_t)n*Hh);
    float a0 = 0.f, a1 = 0.f, a2 = 0.f, a3 = 0.f;
    #pragma unroll
    for (int j = 0; j < 3; j++) {
        int idx = k + j*8;
        float4 hv = hp[idx];
        const float* v0 = sv + 0*Hh + idx*4;
        const float* v1 = sv + 1*Hh + idx*4;
        const float* v2 = sv + 2*Hh + idx*4;
        const float* v3 = sv + 3*Hh + idx*4;
        a0 += hv.x*v0[0] + hv.y*v0[1] + hv.z*v0[2] + hv.w*v0[3];
        a1 += hv.x*v1[0] + hv.y*v1[1] + hv.z*v1[2] + hv.w*v1[3];
        a2 += hv.x*v2[0] + hv.y*v2[1] + hv.z*v2[2] + hv.w*v2[3];
        a3 += hv.x*v3[0] + hv.y*v3[1] + hv.z*v3[2] + hv.w*v3[3];
    }
    #pragma unroll
    for (int off = 4; off > 0; off >>= 1) {
        a0 += __shfl_xor_sync(0xffffffffu, a0, off);
        a1 += __shfl_xor_sync(0xffffffffu, a1, off);
        a2 += __shfl_xor_sync(0xffffffffu, a2, off);
        a3 += __shfl_xor_sync(0xffffffffu, a3, off);
    }
    if (k == 0) {
        g_A[0*Nn + n] = a0; g_A[1*Nn + n] = a1;
        g_A[2*Nn + n] = a2; g_A[3*Nn + n] = a3;
    }
}

// ---------------- merged edge pass over all 3 types ----------------
__global__ void k_edge_all(const int* __restrict__ s0, const int* __restrict__ d0,
                           const int* __restrict__ s1, const int* __restrict__ d1,
                           const int* __restrict__ s2, const int* __restrict__ d2,
                           const float* __restrict__ h, int E0, int E1, int E2)
{
    int W0 = (E0 + 3) >> 2, W1 = (E1 + 3) >> 2, W2 = (E2 + 3) >> 2;
    int gtid = blockIdx.x*blockDim.x + threadIdx.x;
    int w = gtid >> 5;
    int lane = gtid & 31;
    int t, wl, Ew;
    const int *sp, *dp;
    if (w < W0)            { t = 0; wl = w;           Ew = E0; sp = s0; dp = d0; }
    else if (w < W0 + W1)  { t = 1; wl = w - W0;      Ew = E1; sp = s1; dp = d1; }
    else if (w < W0+W1+W2) { t = 2; wl = w - W0 - W1; Ew = E2; sp = s2; dp = d2; }
    else return;

    int k = lane & 7;
    int e = wl*4 + (lane >> 3);
    if (e >= Ew) return;
    int s = sp[e], d = dp[e];
    float w8 = 1.f;
    if (t < 2) {
        float sc = g_A[(2*t)*Nn + s] + g_A[(2*t + 1)*Nn + d];
        sc = sc > 0.f ? sc : 0.01f*sc;   // leaky_relu
        w8 = __expf(sc);                 // max-free softmax (scores bounded)
    }
    if (k == 0) atomicAdd(g_accum + 3*Nn*Hh + t*Nn + d, w8);
    const float4* hp = reinterpret_cast<const float4*>(h + (size_t)s*Hh);
    float* ag = g_accum + (size_t)t*Nn*Hh + (size_t)d*Hh;
    #pragma unroll
    for (int j = 0; j < 3; j++) {
        int idx = k + j*8;
        float4 v = hp[idx];
        if (t < 2) { v.x *= w8; v.y *= w8; v.z *= w8; v.w *= w8; }
        asm volatile("red.global.add.v4.f32 [%0], {%1,%2,%3,%4};"
                     :: "l"(ag + idx*4), "f"(v.x), "f"(v.y), "f"(v.z), "f"(v.w)
                     : "memory");
    }
}

// ---------------- fused scan+fixup (BEFORE combine; combine skips these rows) ----------------
// Detects nodes with any zero-degree edge type and writes their EXACT fp32 output.
__global__ void k_scan_fixup(const float* __restrict__ h, const float* __restrict__ bu,
                             float* __restrict__ out)
{
    __shared__ int list[256];
    __shared__ int cnt;
    int tid = threadIdx.x;
    if (tid == 0) cnt = 0;
    __syncthreads();
    int n = blockIdx.x*256 + tid;
    if (n < Nn) {
        bool bad = false;
        #pragma unroll
        for (int t = 0; t < 3; t++)
            bad |= !(g_accum[3*Nn*Hh + t*Nn + n] > 0.f);
        if (bad) list[atomicAdd(&cnt, 1)] = n;
    }
    __syncthreads();
    int c = cnt;
    int j = tid;
    if (j >= Hh) return;
    for (int i = 0; i < c; i++) {
        int nn = list[i];
        float den[3], ok[3];
        #pragma unroll
        for (int t = 0; t < 3; t++) {
            den[t] = g_accum[3*Nn*Hh + t*Nn + nn];
            ok[t] = (den[t] > 0.f) ? 1.f : 0.f;
        }
        float y = bu[j];
        #pragma unroll
        for (int t = 0; t < 3; t++) y += ok[t]*g_cw[t][j];
        const float* hn = h + (size_t)nn*Hh;
        for (int kk = 0; kk < Hh; kk++) {
            float m = g_Mbig[kk*Hh + j];
            #pragma unroll
            for (int t = 0; t < 3; t++)
                if (ok[t] == 0.f) m -= g_D[t][kk*Hh + j];
            y += hn[kk]*m;
        }
        #pragma unroll
        for (int t = 0; t < 3; t++) {
            if (ok[t] != 0.f) {
                float rd = 1.f/den[t];
                const float* agg = g_accum + (size_t)t*Nn*Hh + (size_t)nn*Hh;
                for (int kk = 0; kk < Hh; kk++)
                    y += agg[kk]*rd*g_Mbig[(Hh + t*Hh + kk)*Hh + j];
            }
        }
        out[(size_t)nn*Hh + j] = fmaxf(y, 0.f);
    }
}

// ---------------- mma helpers (legacy mma.sync, sm_80+) ----------------
__device__ __forceinline__ uint32_t smem_u32(const void* p) {
    uint32_t a;
    asm("{ .reg .u64 t; cvta.to.shared.u64 t, %1; cvt.u32.u64 %0, t; }" : "=r"(a) : "l"(p));
    return a;
}
__device__ __forceinline__ void ldsm4(uint32_t* r, uint32_t addr) {
    asm volatile("ldmatrix.sync.aligned.m8n8.x4.shared.b16 {%0,%1,%2,%3}, [%4];"
        : "=r"(r[0]), "=r"(r[1]), "=r"(r[2]), "=r"(r[3]) : "r"(addr));
}
__device__ __forceinline__ void mma16816(float* c, const uint32_t* a, const uint32_t* b) {
    asm volatile("mma.sync.aligned.m16n8k16.row.col.f32.bf16.bf16.f32 "
        "{%0,%1,%2,%3}, {%4,%5,%6,%7}, {%8,%9}, {%0,%1,%2,%3};"
        : "+f"(c[0]), "+f"(c[1]), "+f"(c[2]), "+f"(c[3])
        : "r"(a[0]), "r"(a[1]), "r"(a[2]), "r"(a[3]), "r"(b[0]), "r"(b[1]));
}

// ---------------- mma combine: out = relu([h|G0s|G1s|G2s] @ Mbig + bu2) ----------------
// 64 rows x 96 cols per block, register-prefetched one K-chunk ahead.
// Zeroes agg + den in place after reading (restores graph-replay invariant).
// Skips storing rows handled by scan_fixup (any Ss==0).
#define PITCH 144
#define OF_BU2 0
#define OF_SS  512
#define OF_AHI 2048
#define OF_ALO (OF_AHI + 64*PITCH)    // 11264
#define OF_BHI (OF_ALO + 64*PITCH)    // 20480
#define OF_BLO (OF_BHI + 96*PITCH)    // 34304
#define SM_TOT (OF_BLO + 96*PITCH)    // 48128

__global__ void __launch_bounds__(256, 2) k_combine_mma(const float* __restrict__ h,
                                                        float* __restrict__ out)
{
    extern __shared__ char smem[];
    uint32_t sb = smem_u32(smem);
    float* bu2s = reinterpret_cast<float*>(smem + OF_BU2);
    float* Ss   = reinterpret_cast<float*>(smem + OF_SS);   // [3][64]
    int tid = threadIdx.x;
    int row0 = blockIdx.x * 64;

    if (tid < 96) bu2s[tid] = g_bu2[tid];
    if (tid < 3*64) {
        int t = tid >> 6, r = tid & 63;
        int n = row0 + r;
        float dn = 0.f;
        if (n < Nn) {
            dn = g_accum[3*Nn*Hh + t*Nn + n];
            g_accum[3*Nn*Hh + t*Nn + n] = 0.f;   // reset for next replay
        }
        Ss[t*64 + r] = (dn > 0.f) ? 1.f/dn : 0.f;
    }
    __syncthreads();

    int lane = tid & 31, w = tid >> 5;
    int warp_m = w & 3, warp_n = w >> 2;      // 4(m) x 2(n)
    int g = lane >> 2, t4 = lane & 3;
    int q = lane >> 3, rr = lane & 7;

    float acc[6][4];
    #pragma unroll
    for (int j = 0; j < 6; j++)
        #pragma unroll
        for (int v = 0; v < 4; v++) acc[j][v] = 0.f;

    int aRow = warp_m*16 + (q & 1)*8 + rr;
    int aColB = (q >> 1)*8;
    int bRow = warp_n*48 + (q >> 1)*8 + rr;
    int bColB = (q & 1)*8;

    float4 av[4];
    uint2  bvh[6], bvl[6];
    const float4 F4Z = make_float4(0.f, 0.f, 0.f, 0.f);

    // ---- prefetch chunk 0 (zero agg after read) ----
    {
        const int kin = 0;
        #pragma unroll
        for (int p = 0; p < 4; p++) {
            int li = tid + p*256;
            int r = li >> 4, cg = li & 15;
            int kglob = kin + cg*4;
            int seg = kglob / Hh, kloc = kglob - seg*Hh;
            int n = row0 + r;
            av[p] = F4Z;
            if (n < Nn) {
                if (seg == 0) {
                    av[p] = *reinterpret_cast<const float4*>(h + (size_t)n*Hh + kloc);
                } else {
                    float* gp = g_accum + (size_t)(seg-1)*Nn*Hh + (size_t)n*Hh + kloc;
                    av[p] = *reinterpret_cast<float4*>(gp);
                    *reinterpret_cast<float4*>(gp) = F4Z;
                }
            }
        }
        #pragma unroll
        for (int p = 0; p < 6; p++) {
            int li = tid + p*256;
            int j = li >> 4, gg = li & 15;
            bvh[p] = *reinterpret_cast<const uint2*>(g_MbT_hi + j*384 + kin + gg*4);
            bvl[p] = *reinterpret_cast<const uint2*>(g_MbT_lo + j*384 + kin + gg*4);
        }
    }

    #pragma unroll
    for (int c = 0; c < 6; c++) {
        const int kin = c*64;
        // ---- store prefetched regs to smem (scale + split A) ----
        #pragma unroll
        for (int p = 0; p < 4; p++) {
            int li = tid + p*256;
            int r = li >> 4, cg = li & 15;
            int kglob = kin + cg*4;
            int seg = kglob / Hh;
            float4 v = av[p];
            if (seg) {
                float s = Ss[(seg-1)*64 + r];
                v.x *= s; v.y *= s; v.z *= s; v.w *= s;
            }
            __nv_bfloat162 h01 = __floats2bfloat162_rn(v.x, v.y);
            __nv_bfloat162 h23 = __floats2bfloat162_rn(v.z, v.w);
            __nv_bfloat162 l01 = __floats2bfloat162_rn(v.x - __bfloat162float(h01.x),
                                                       v.y - __bfloat162float(h01.y));
            __nv_bfloat162 l23 = __floats2bfloat162_rn(v.z - __bfloat162float(h23.x),
                                                       v.w - __bfloat162float(h23.y));
            uint32_t off = (uint32_t)(r*PITCH + cg*8);
            *reinterpret_cast<__nv_bfloat162*>(smem + OF_AHI + off)     = h01;
            *reinterpret_cast<__nv_bfloat162*>(smem + OF_AHI + off + 4) = h23;
            *reinterpret_cast<__nv_bfloat162*>(smem + OF_ALO + off)     = l01;
            *reinterpret_cast<__nv_bfloat162*>(smem + OF_ALO + off + 4) = l23;
        }
        #pragma unroll
        for (int p = 0; p < 6; p++) {
            int li = tid + p*256;
            int j = li >> 4, gg = li & 15;
            uint32_t off = (uint32_t)(j*PITCH + gg*8);
            *reinterpret_cast<uint2*>(smem + OF_BHI + off) = bvh[p];
            *reinterpret_cast<uint2*>(smem + OF_BLO + off) = bvl[p];
        }
        __syncthreads();
        // ---- prefetch next chunk (overlaps MMA below; zero agg after read) ----
        if (c < 5) {
            const int kin2 = kin + 64;
            #pragma unroll
            for (int p = 0; p < 4; p++) {
                int li = tid + p*256;
                int r = li >> 4, cg = li & 15;
                int kglob = kin2 + cg*4;
                int seg = kglob / Hh, kloc = kglob - seg*Hh;
                int n = row0 + r;
                av[p] = F4Z;
                if (n < Nn) {
                    if (seg == 0) {
                        av[p] = *reinterpret_cast<const float4*>(h + (size_t)n*Hh + kloc);
                    } else {
                        float* gp = g_accum + (size_t)(seg-1)*Nn*Hh + (size_t)n*Hh + kloc;
                        av[p] = *reinterpret_cast<float4*>(gp);
                        *reinterpret_cast<float4*>(gp) = F4Z;
                    }
                }
            }
            #pragma unroll
            for (int p = 0; p < 6; p++) {
                int li = tid + p*256;
                int j = li >> 4, gg = li & 15;
                bvh[p] = *reinterpret_cast<const uint2*>(g_MbT_hi + j*384 + kin2 + gg*4);
                bvl[p] = *reinterpret_cast<const uint2*>(g_MbT_lo + j*384 + kin2 + gg*4);
            }
        }
        // ---- MMA: 4 k16 steps, term-major ----
        #pragma unroll
        for (int ks = 0; ks < 4; ks++) {
            int k0 = ks*16;
            uint32_t ah[4], al[4];
            uint32_t ao = (uint32_t)(aRow*PITCH + (k0 + aColB)*2);
            ldsm4(ah, sb + OF_AHI + ao);
            ldsm4(al, sb + OF_ALO + ao);
            uint32_t bh[3][4], bl[3][4];
            #pragma unroll
            for (int pr = 0; pr < 3; pr++) {
                uint32_t bo = (uint32_t)((bRow + pr*16)*PITCH + (k0 + bColB)*2);
                ldsm4(bh[pr], sb + OF_BHI + bo);
                ldsm4(bl[pr], sb + OF_BLO + bo);
            }
            #pragma unroll
            for (int pr = 0; pr < 3; pr++)
                #pragma unroll
                for (int hf = 0; hf < 2; hf++)
                    mma16816(acc[pr*2+hf], ah, bh[pr] + hf*2);
            #pragma unroll
            for (int pr = 0; pr < 3; pr++)
                #pragma unroll
                for (int hf = 0; hf < 2; hf++)
                    mma16816(acc[pr*2+hf], ah, bl[pr] + hf*2);
            #pragma unroll
            for (int pr = 0; pr < 3; pr++)
                #pragma unroll
                for (int hf = 0; hf < 2; hf++)
                    mma16816(acc[pr*2+hf], al, bh[pr] + hf*2);
        }
        __syncthreads();
    }

    // ---- epilogue: bias + relu; skip rows scan_fixup already wrote ----
    int r0 = warp_m*16 + g;
    int r1 = r0 + 8;
    bool def0 = (Ss[r0] == 0.f) | (Ss[64 + r0] == 0.f) | (Ss[128 + r0] == 0.f);
    bool def1 = (Ss[r1] == 0.f) | (Ss[64 + r1] == 0.f) | (Ss[128 + r1] == 0.f);
    int n0 = row0 + r0;
    #pragma unroll
    for (int nt = 0; nt < 6; nt++) {
        int col = warp_n*48 + nt*8 + t4*2;
        float b0 = bu2s[col], b1 = bu2s[col+1];
        if (n0 < Nn && !def0) {
            float2 o;
            o.x = fmaxf(acc[nt][0] + b0, 0.f);
            o.y = fmaxf(acc[nt][1] + b1, 0.f);
            *reinterpret_cast<float2*>(out + (size_t)n0*Hh + col) = o;
        }
        if (n0 + 8 < Nn && !def1) {
            float2 o;
            o.x = fmaxf(acc[nt][2] + b0, 0.f);
            o.y = fmaxf(acc[nt][3] + b1, 0.f);
            *reinterpret_cast<float2*>(out + (size_t)(n0+8)*Hh + col) = o;
        }
    }
}

// ---------------- launch ----------------
extern "C" void kernel_launch(void* const* d_in, const int* in_sizes, int n_in,
                              void* d_out, int out_size)
{
    const float* h    = (const float*)d_in[0];
    const int*   src0 = (const int*)d_in[1];
    const int*   dst0 = (const int*)d_in[2];
    const int*   src1 = (const int*)d_in[3];
    const int*   dst1 = (const int*)d_in[4];
    const int*   src2 = (const int*)d_in[5];
    const int*   dst2 = (const int*)d_in[6];
    const float* Wm0 = (const float*)d_in[7];
    const float* bm0 = (const float*)d_in[8];
    const float* ef0 = (const float*)d_in[9];
    const float* Wm1 = (const float*)d_in[10];
    const float* bm1 = (const float*)d_in[11];
    const float* ef1 = (const float*)d_in[12];
    const float* Wm2 = (const float*)d_in[13];
    const float* bm2 = (const float*)d_in[14];
    const float* ef2 = (const float*)d_in[15];
    const float* Wn0 = (const float*)d_in[16];
    const float* Wa0 = (const float*)d_in[17];
    const float* Wn1 = (const float*)d_in[18];
    const float* Wa1 = (const float*)d_in[19];
    const float* Wu  = (const float*)d_in[20];
    const float* bu  = (const float*)d_in[21];
    float* out = (float*)d_out;

    int E0 = in_sizes[1], E1 = in_sizes[3], E2 = in_sizes[5];

    int Wtot = (E0 + 3)/4 + (E1 + 3)/4 + (E2 + 3)/4;
    int edge_blocks = (Wtot*32 + 255)/256;

    static int smem_set = 0;
    if (!smem_set) {
        cudaFuncSetAttribute(k_combine_mma, cudaFuncAttributeMaxDynamicSharedMemorySize, SM_TOT);
        smem_set = 1;
    }

    // 5 launches. g_accum invariant: zero at entry, re-zeroed by combine.
    k_prep<<<PREP_BLOCKS, 256>>>(Wn0, Wa0, Wn1, Wa1,
                            Wm0, bm0, ef0, Wm1, bm1, ef1, Wm2, bm2, ef2, Wu, bu);
    k_anode_bt<<<ANODE_BLOCKS + BT_BLOCKS, 256>>>(h);
    k_edge_all<<<edge_blocks, 256>>>(src0, dst0, src1, dst1, src2, dst2, h, E0, E1, E2);
    k_scan_fixup<<<(Nn + 255)/256, 256>>>(h, bu, out);
    k_combine_mma<<<(Nn + 63)/64, 256, SM_TOT>>>(h, out);
}

// round 15
// speedup vs baseline: 2.3049x; 2.3049x over previous
#include <cuda_runtime.h>
#include <cuda_bf16.h>
#include <cstdint>

#define Nn 100000
#define Hh 96

typedef unsigned long long u64;

// ---------------- static device scratch (no allocations allowed) ----------------
__device__ __align__(16) float g_accum[3*Nn*Hh + 3*Nn];  // agg0,agg1,agg2 then den0,den1,den2
__device__ __align__(16) float g_A[4*Nn];                // aS0, aD0, aS1, aD1
__device__ __align__(16) float g_Mbig[384*Hh];           // rows 0-95: M0, then M1_t (t=0..2)
__device__ __align__(16) float g_D[3][Hh*Hh];            // WmDst_t @ Wu_t
__device__ __align__(16) float g_V[4*Hh];                // attention vectors
__device__ __align__(16) float g_cw[3][Hh];              // c_t @ Wu_t
__device__ __align__(16) float g_bu2[Hh];                // bu + sum cw
__device__ __align__(16) float g_rden[3*Nn];
__device__ __align__(16) __nv_bfloat16 g_MbT_hi[Hh*384]; // B^T split: [j][k]
__device__ __align__(16) __nv_bfloat16 g_MbT_lo[Hh*384];
__device__ int g_defList[Nn];
__device__ int g_defCount;

// ---------------- fused zero + prep (independent outputs) ----------------
#define ZERO_BLOCKS 2048
#define PREP_ITEMS  (3*Hh*Hh + Hh*Hh + 2*Hh)
#define PREP_BLOCKS ((PREP_ITEMS + 255)/256)

__global__ void k_zero_prep(
    const float* __restrict__ Wn0, const float* __restrict__ Wa0,
    const float* __restrict__ Wn1, const float* __restrict__ Wa1,
    const float* __restrict__ Wm0, const float* __restrict__ bm0, const float* __restrict__ ef0,
    const float* __restrict__ Wm1, const float* __restrict__ bm1, const float* __restrict__ ef1,
    const float* __restrict__ Wm2, const float* __restrict__ bm2, const float* __restrict__ ef2,
    const float* __restrict__ Wu, const float* __restrict__ bu)
{
    if (blockIdx.x < ZERO_BLOCKS) {
        const int n4 = (3*Nn*Hh + 3*Nn) / 4;
        float4 z = make_float4(0.f, 0.f, 0.f, 0.f);
        float4* p = reinterpret_cast<float4*>(g_accum);
        for (int i = blockIdx.x*blockDim.x + threadIdx.x; i < n4; i += ZERO_BLOCKS*blockDim.x)
            p[i] = z;
        if (blockIdx.x == 0 && threadIdx.x == 0) g_defCount = 0;
        return;
    }
    const int NA = 3*Hh*Hh;
    const int NB = Hh*Hh;
    int idx = (blockIdx.x - ZERO_BLOCKS)*blockDim.x + threadIdx.x;
    const float* Wms[3] = {Wm0, Wm1, Wm2};
    const float* bms[3] = {bm0, bm1, bm2};
    const float* efs[3] = {ef0, ef1, ef2};

    if (idx < NA) {
        int t = idx / (Hh*Hh);
        int r = idx % (Hh*Hh);
        int k = r / Hh, j = r % Hh;
        const float* Wm = Wms[t];
        float m1 = 0.f, dd = 0.f;
        const float* wuBase = Wu + (Hh + t*Hh)*Hh + j;
        for (int c = 0; c < Hh; c++) {
            float wu = wuBase[c*Hh];
            m1 += Wm[k*Hh + c] * wu;
            dd += Wm[(Hh + k)*Hh + c] * wu;
        }
        g_Mbig[(Hh + t*Hh + k)*Hh + j] = m1;
        g_D[t][k*Hh + j] = dd;
    } else if (idx < NA + NB) {
        int r = idx - NA;
        int k = r / Hh, j = r % Hh;
        float m0 = Wu[k*Hh + j];
        #pragma unroll
        for (int t = 0; t < 3; t++) {
            const float* Wm = Wms[t];
            const float* wuBase = Wu + (Hh + t*Hh)*Hh + j;
            for (int c = 0; c < Hh; c++)
                m0 += Wm[(Hh + k)*Hh + c] * wuBase[c*Hh];
        }
        g_Mbig[k*Hh + j] = m0;
    } else if (idx < NA + NB + Hh) {
        int i = idx - NA - NB;
        float s0 = 0.f, d0 = 0.f, s1 = 0.f, d1 = 0.f;
        for (int j = 0; j < 32; j++) {
            float w0 = Wn0[i*32+j], w1 = Wn1[i*32+j];
            s0 += w0*Wa0[j];     d0 += w0*Wa0[32+j];
            s1 += w1*Wa1[j];     d1 += w1*Wa1[32+j];
        }
        g_V[0*Hh+i] = s0; g_V[1*Hh+i] = d0; g_V[2*Hh+i] = s1; g_V[3*Hh+i] = d1;
    } else if (idx < NA + NB + 2*Hh) {
        int i = idx - NA - NB - Hh;
        float b = bu[i];
        #pragma unroll
        for (int t = 0; t < 3; t++) {
            float cw = 0.f;
            for (int c = 0; c < Hh; c++) {
                float ct = bms[t][c];
                for (int d = 0; d < 16; d++) ct += efs[t][d] * Wms[t][(192+d)*Hh + c];
                cw += ct * Wu[(Hh + t*Hh + c)*Hh + i];
            }
            g_cw[t][i] = cw;
            b += cw;
        }
        g_bu2[i] = b;
    }
}

// ---------------- anode + B-transpose/split fused ----------------
#define ANODE_BLOCKS (((Nn + 3)/4*32 + 255)/256)
#define BT_BLOCKS    ((Hh*384 + 255)/256)

__global__ void k_anode_bt(const float* __restrict__ h) {
    if (blockIdx.x >= ANODE_BLOCKS) {
        int idx = (blockIdx.x - ANODE_BLOCKS)*blockDim.x + threadIdx.x;
        if (idx >= Hh*384) return;
        int j = idx / 384, k = idx % 384;
        float v = g_Mbig[k*Hh + j];
        __nv_bfloat16 hi = __float2bfloat16_rn(v);
        __nv_bfloat16 lo = __float2bfloat16_rn(v - __bfloat162float(hi));
        g_MbT_hi[idx] = hi;
        g_MbT_lo[idx] = lo;
        return;
    }
    __shared__ float sv[4*Hh];
    for (int i = threadIdx.x; i < 4*Hh; i += blockDim.x) sv[i] = g_V[i];
    __syncthreads();
    int gtid = blockIdx.x*blockDim.x + threadIdx.x;
    int lane = gtid & 31;
    int k = lane & 7;
    int n = (gtid >> 5)*4 + (lane >> 3);
    if (n >= Nn) return;
    const float4* hp = reinterpret_cast<const float4*>(h + (size_t)n*Hh);
    float a0 = 0.f, a1 = 0.f, a2 = 0.f, a3 = 0.f;
    #pragma unroll
    for (int j = 0; j < 3; j++) {
        int idx = k + j*8;
        float4 hv = hp[idx];
        const float* v0 = sv + 0*Hh + idx*4;
        const float* v1 = sv + 1*Hh + idx*4;
        const float* v2 = sv + 2*Hh + idx*4;
        const float* v3 = sv + 3*Hh + idx*4;
        a0 += hv.x*v0[0] + hv.y*v0[1] + hv.z*v0[2] + hv.w*v0[3];
        a1 += hv.x*v1[0] + hv.y*v1[1] + hv.z*v1[2] + hv.w*v1[3];
        a2 += hv.x*v2[0] + hv.y*v2[1] + hv.z*v2[2] + hv.w*v2[3];
        a3 += hv.x*v3[0] + hv.y*v3[1] + hv.z*v3[2] + hv.w*v3[3];
    }
    #pragma unroll
    for (int off = 4; off > 0; off >>= 1) {
        a0 += __shfl_xor_sync(0xffffffffu, a0, off);
        a1 += __shfl_xor_sync(0xffffffffu, a1, off);
        a2 += __shfl_xor_sync(0xffffffffu, a2, off);
        a3 += __shfl_xor_sync(0xffffffffu, a3, off);
    }
    if (k == 0) {
        g_A[0*Nn + n] = a0; g_A[1*Nn + n] = a1;
        g_A[2*Nn + n] = a2; g_A[3*Nn + n] = a3;
    }
}

// ---------------- merged edge pass over all 3 types ----------------
// h[src] loaded with ld.global.cg (L2-only): random-gather rows have no L1 reuse,
// so keeping them out of L1 relieves the L1tex wavefront bottleneck (86.5% in R9).
__global__ void k_edge_all(const int* __restrict__ s0, const int* __restrict__ d0,
                           const int* __restrict__ s1, const int* __restrict__ d1,
                           const int* __restrict__ s2, const int* __restrict__ d2,
                           const float* __restrict__ h, int E0, int E1, int E2)
{
    int W0 = (E0 + 3) >> 2, W1 = (E1 + 3) >> 2, W2 = (E2 + 3) >> 2;
    int gtid = blockIdx.x*blockDim.x + threadIdx.x;
    int w = gtid >> 5;
    int lane = gtid & 31;
    int t, wl, Ew;
    const int *sp, *dp;
    if (w < W0)            { t = 0; wl = w;           Ew = E0; sp = s0; dp = d0; }
    else if (w < W0 + W1)  { t = 1; wl = w - W0;      Ew = E1; sp = s1; dp = d1; }
    else if (w < W0+W1+W2) { t = 2; wl = w - W0 - W1; Ew = E2; sp = s2; dp = d2; }
    else return;

    int k = lane & 7;
    int e = wl*4 + (lane >> 3);
    if (e >= Ew) return;
    int s = sp[e], d = dp[e];
    float w8 = 1.f;
    if (t < 2) {
        float sc = g_A[(2*t)*Nn + s] + g_A[(2*t + 1)*Nn + d];
        sc = sc > 0.f ? sc : 0.01f*sc;   // leaky_relu
        w8 = __expf(sc);                 // max-free softmax (scores bounded)
    }
    if (k == 0) atomicAdd(g_accum + 3*Nn*Hh + t*Nn + d, w8);
    const float* hp = h + (size_t)s*Hh;
    float* ag = g_accum + (size_t)t*Nn*Hh + (size_t)d*Hh;
    #pragma unroll
    for (int j = 0; j < 3; j++) {
        int idx = k + j*8;
        float4 v;
        asm volatile("ld.global.cg.v4.f32 {%0,%1,%2,%3}, [%4];"
                     : "=f"(v.x), "=f"(v.y), "=f"(v.z), "=f"(v.w)
                     : "l"(hp + idx*4));
        if (t < 2) { v.x *= w8; v.y *= w8; v.z *= w8; v.w *= w8; }
        asm volatile("red.global.add.v4.f32 [%0], {%1,%2,%3,%4};"
                     :: "l"(ag + idx*4), "f"(v.x), "f"(v.y), "f"(v.z), "f"(v.w)
                     : "memory");
    }
}

// ---------------- scan: reciprocal denominators + deficient-node list ----------------
__global__ void k_scan() {
    int n = blockIdx.x*blockDim.x + threadIdx.x;
    if (n >= Nn) return;
    bool bad = false;
    #pragma unroll
    for (int t = 0; t < 3; t++) {
        float dn = g_accum[3*Nn*Hh + t*Nn + n];
        bool ok = dn > 0.f;
        g_rden[t*Nn + n] = ok ? 1.f/dn : 0.f;
        bad |= !ok;
    }
    if (bad) {
        int p = atomicAdd(&g_defCount, 1);
        g_defList[p] = n;
    }
}

// ---------------- mma helpers (legacy mma.sync, sm_80+) ----------------
__device__ __forceinline__ uint32_t smem_u32(const void* p) {
    uint32_t a;
    asm("{ .reg .u64 t; cvta.to.shared.u64 t, %1; cvt.u32.u64 %0, t; }" : "=r"(a) : "l"(p));
    return a;
}
__device__ __forceinline__ void ldsm4(uint32_t* r, uint32_t addr) {
    asm volatile("ldmatrix.sync.aligned.m8n8.x4.shared.b16 {%0,%1,%2,%3}, [%4];"
        : "=r"(r[0]), "=r"(r[1]), "=r"(r[2]), "=r"(r[3]) : "r"(addr));
}
__device__ __forceinline__ void mma16816(float* c, const uint32_t* a, const uint32_t* b) {
    asm volatile("mma.sync.aligned.m16n8k16.row.col.f32.bf16.bf16.f32 "
        "{%0,%1,%2,%3}, {%4,%5,%6,%7}, {%8,%9}, {%0,%1,%2,%3};"
        : "+f"(c[0]), "+f"(c[1]), "+f"(c[2]), "+f"(c[3])
        : "r"(a[0]), "r"(a[1]), "r"(a[2]), "r"(a[3]), "r"(b[0]), "r"(b[1]));
}

// ---------------- mma combine: out = relu([h|G0s|G1s|G2s] @ Mbig + bu2) ----------------
// 64 rows x 96 cols per block (2 blocks/SM), register-prefetched one K-chunk ahead.
#define PITCH 144
#define OF_BU2 0
#define OF_SS  512
#define OF_AHI 2048
#define OF_ALO (OF_AHI + 64*PITCH)    // 11264
#define OF_BHI (OF_ALO + 64*PITCH)    // 20480
#define OF_BLO (OF_BHI + 96*PITCH)    // 34304
#define SM_TOT (OF_BLO + 96*PITCH)    // 48128

__global__ void __launch_bounds__(256, 2) k_combine_mma(const float* __restrict__ h,
                                                        float* __restrict__ out)
{
    extern __shared__ char smem[];
    uint32_t sb = smem_u32(smem);
    float* bu2s = reinterpret_cast<float*>(smem + OF_BU2);
    float* Ss   = reinterpret_cast<float*>(smem + OF_SS);   // [3][64]
    int tid = threadIdx.x;
    int row0 = blockIdx.x * 64;

    if (tid < 96) bu2s[tid] = g_bu2[tid];
    if (tid < 3*64) {
        int t = tid / 64, r = tid % 64;
        int n = row0 + r;
        float dn = (n < Nn) ? g_accum[3*Nn*Hh + t*Nn + n] : 0.f;
        Ss[t*64 + r] = (dn > 0.f) ? 1.f/dn : 0.f;
    }
    __syncthreads();

    int lane = tid & 31, w = tid >> 5;
    int warp_m = w & 3, warp_n = w >> 2;      // 4(m) x 2(n)
    int g = lane >> 2, t4 = lane & 3;
    int q = lane >> 3, rr = lane & 7;

    float acc[6][4];
    #pragma unroll
    for (int j = 0; j < 6; j++)
        #pragma unroll
        for (int v = 0; v < 4; v++) acc[j][v] = 0.f;

    int aRow = warp_m*16 + (q & 1)*8 + rr;
    int aColB = (q >> 1)*8;
    int bRow = warp_n*48 + (q >> 1)*8 + rr;
    int bColB = (q & 1)*8;

    float4 av[4];
    uint2  bvh[6], bvl[6];

    // ---- prefetch chunk 0 ----
    {
        const int kin = 0;
        #pragma unroll
        for (int p = 0; p < 4; p++) {
            int li = tid + p*256;
            int r = li >> 4, cg = li & 15;
            int kglob = kin + cg*4;
            int seg = kglob / Hh, kloc = kglob - seg*Hh;
            int n = row0 + r;
            av[p] = make_float4(0.f, 0.f, 0.f, 0.f);
            if (n < Nn) {
                const float* sp = (seg == 0)
                    ? (h + (size_t)n*Hh + kloc)
                    : (g_accum + (size_t)(seg-1)*Nn*Hh + (size_t)n*Hh + kloc);
                av[p] = *reinterpret_cast<const float4*>(sp);
            }
        }
        #pragma unroll
        for (int p = 0; p < 6; p++) {
            int li = tid + p*256;
            int j = li >> 4, gg = li & 15;
            bvh[p] = *reinterpret_cast<const uint2*>(g_MbT_hi + j*384 + kin + gg*4);
            bvl[p] = *reinterpret_cast<const uint2*>(g_MbT_lo + j*384 + kin + gg*4);
        }
    }

    #pragma unroll
    for (int c = 0; c < 6; c++) {
        const int kin = c*64;
        // ---- store prefetched regs to smem (convert/split A, apply scale) ----
        #pragma unroll
        for (int p = 0; p < 4; p++) {
            int li = tid + p*256;
            int r = li >> 4, cg = li & 15;
            int kglob = kin + cg*4;
            int seg = kglob / Hh;
            float4 v = av[p];
            if (seg) {
                float s = Ss[(seg-1)*64 + r];
                v.x *= s; v.y *= s; v.z *= s; v.w *= s;
            }
            __nv_bfloat162 h01 = __floats2bfloat162_rn(v.x, v.y);
            __nv_bfloat162 h23 = __floats2bfloat162_rn(v.z, v.w);
            __nv_bfloat162 l01 = __floats2bfloat162_rn(v.x - __bfloat162float(h01.x),
                                                       v.y - __bfloat162float(h01.y));
            __nv_bfloat162 l23 = __floats2bfloat162_rn(v.z - __bfloat162float(h23.x),
                                                       v.w - __bfloat162float(h23.y));
            uint32_t off = (uint32_t)(r*PITCH + cg*8);
            *reinterpret_cast<__nv_bfloat162*>(smem + OF_AHI + off)     = h01;
            *reinterpret_cast<__nv_bfloat162*>(smem + OF_AHI + off + 4) = h23;
            *reinterpret_cast<__nv_bfloat162*>(smem + OF_ALO + off)     = l01;
            *reinterpret_cast<__nv_bfloat162*>(smem + OF_ALO + off + 4) = l23;
        }
        #pragma unroll
        for (int p = 0; p < 6; p++) {
            int li = tid + p*256;
            int j = li >> 4, gg = li & 15;
            uint32_t off = (uint32_t)(j*PITCH + gg*8);
            *reinterpret_cast<uint2*>(smem + OF_BHI + off) = bvh[p];
            *reinterpret_cast<uint2*>(smem + OF_BLO + off) = bvl[p];
        }
        __syncthreads();
        // ---- prefetch next chunk (global loads overlap MMA below) ----
        if (c < 5) {
            const int kin2 = kin + 64;
            #pragma unroll
            for (int p = 0; p < 4; p++) {
                int li = tid + p*256;
                int r = li >> 4, cg = li & 15;
                int kglob = kin2 + cg*4;
                int seg = kglob / Hh, kloc = kglob - seg*Hh;
                int n = row0 + r;
                av[p] = make_float4(0.f, 0.f, 0.f, 0.f);
                if (n < Nn) {
                    const float* sp = (seg == 0)
                        ? (h + (size_t)n*Hh + kloc)
                        : (g_accum + (size_t)(seg-1)*Nn*Hh + (size_t)n*Hh + kloc);
                    av[p] = *reinterpret_cast<const float4*>(sp);
                }
            }
            #pragma unroll
            for (int p = 0; p < 6; p++) {
                int li = tid + p*256;
                int j = li >> 4, gg = li & 15;
                bvh[p] = *reinterpret_cast<const uint2*>(g_MbT_hi + j*384 + kin2 + gg*4);
                bvl[p] = *reinterpret_cast<const uint2*>(g_MbT_lo + j*384 + kin2 + gg*4);
            }
        }
        // ---- MMA: 4 k16 steps, term-major ----
        #pragma unroll
        for (int ks = 0; ks < 4; ks++) {
            int k0 = ks*16;
            uint32_t ah[4], al[4];
            uint32_t ao = (uint32_t)(aRow*PITCH + (k0 + aColB)*2);
            ldsm4(ah, sb + OF_AHI + ao);
            ldsm4(al, sb + OF_ALO + ao);
            uint32_t bh[3][4], bl[3][4];
            #pragma unroll
            for (int pr = 0; pr < 3; pr++) {
                uint32_t bo = (uint32_t)((bRow + pr*16)*PITCH + (k0 + bColB)*2);
                ldsm4(bh[pr], sb + OF_BHI + bo);
                ldsm4(bl[pr], sb + OF_BLO + bo);
            }
            #pragma unroll
            for (int pr = 0; pr < 3; pr++)
                #pragma unroll
                for (int hf = 0; hf < 2; hf++)
                    mma16816(acc[pr*2+hf], ah, bh[pr] + hf*2);
            #pragma unroll
            for (int pr = 0; pr < 3; pr++)
                #pragma unroll
                for (int hf = 0; hf < 2; hf++)
                    mma16816(acc[pr*2+hf], ah, bl[pr] + hf*2);
            #pragma unroll
            for (int pr = 0; pr < 3; pr++)
                #pragma unroll
                for (int hf = 0; hf < 2; hf++)
                    mma16816(acc[pr*2+hf], al, bh[pr] + hf*2);
        }
        __syncthreads();
    }

    // ---- epilogue: bias + relu, float2 stores ----
    int n0 = row0 + warp_m*16 + g;
    #pragma unroll
    for (int nt = 0; nt < 6; nt++) {
        int col = warp_n*48 + nt*8 + t4*2;
        float b0 = bu2s[col], b1 = bu2s[col+1];
        if (n0 < Nn) {
            float2 o;
            o.x = fmaxf(acc[nt][0] + b0, 0.f);
            o.y = fmaxf(acc[nt][1] + b1, 0.f);
            *reinterpret_cast<float2*>(out + (size_t)n0*Hh + col) = o;
        }
        if (n0 + 8 < Nn) {
            float2 o;
            o.x = fmaxf(acc[nt][2] + b0, 0.f);
            o.y = fmaxf(acc[nt][3] + b1, 0.f);
            *reinterpret_cast<float2*>(out + (size_t)(n0+8)*Hh + col) = o;
        }
    }
}

// ---------------- fixup for nodes with a zero-degree edge type (exact fp32) ----------------
__global__ void k_fixup(const float* __restrict__ h, const float* __restrict__ bu,
                        float* __restrict__ out)
{
    int cnt = g_defCount;
    int j = threadIdx.x;   // 96 threads
    for (int i = blockIdx.x; i < cnt; i += gridDim.x) {
        int n = g_defList[i];
        float ok[3];
        #pragma unroll
        for (int t = 0; t < 3; t++)
            ok[t] = (g_accum[3*Nn*Hh + t*Nn + n] > 0.f) ? 1.f : 0.f;
        float y = bu[j];
        #pragma unroll
        for (int t = 0; t < 3; t++) y += ok[t]*g_cw[t][j];
        const float* hn = h + (size_t)n*Hh;
        for (int kk = 0; kk < Hh; kk++) {
            float m = g_Mbig[kk*Hh + j];
            #pragma unroll
            for (int t = 0; t < 3; t++)
                if (ok[t] == 0.f) m -= g_D[t][kk*Hh + j];
            y += hn[kk]*m;
        }
        #pragma unroll
        for (int t = 0; t < 3; t++) {
            if (ok[t] != 0.f) {
                float rd = g_rden[t*Nn + n];
                const float* agg = g_accum + (size_t)t*Nn*Hh + (size_t)n*Hh;
                for (int kk = 0; kk < Hh; kk++)
                    y += agg[kk]*rd*g_Mbig[(Hh + t*Hh + kk)*Hh + j];
            }
        }
        out[(size_t)n*Hh + j] = fmaxf(y, 0.f);
    }
}

// ---------------- launch ----------------
extern "C" void kernel_launch(void* const* d_in, const int* in_sizes, int n_in,
                              void* d_out, int out_size)
{
    const float* h    = (const float*)d_in[0];
    const int*   src0 = (const int*)d_in[1];
    const int*   dst0 = (const int*)d_in[2];
    const int*   src1 = (const int*)d_in[3];
    const int*   dst1 = (const int*)d_in[4];
    const int*   src2 = (const int*)d_in[5];
    const int*   dst2 = (const int*)d_in[6];
    const float* Wm0 = (const float*)d_in[7];
    const float* bm0 = (const float*)d_in[8];
    const float* ef0 = (const float*)d_in[9];
    const float* Wm1 = (const float*)d_in[10];
    const float* bm1 = (const float*)d_in[11];
    const float* ef1 = (const float*)d_in[12];
    const float* Wm2 = (const float*)d_in[13];
    const float* bm2 = (const float*)d_in[14];
    const float* ef2 = (const float*)d_in[15];
    const float* Wn0 = (const float*)d_in[16];
    const float* Wa0 = (const float*)d_in[17];
    const float* Wn1 = (const float*)d_in[18];
    const float* Wa1 = (const float*)d_in[19];
    const float* Wu  = (const float*)d_in[20];
    const float* bu  = (const float*)d_in[21];
    float* out = (float*)d_out;

    int E0 = in_sizes[1], E1 = in_sizes[3], E2 = in_sizes[5];

    int Wtot = (E0 + 3)/4 + (E1 + 3)/4 + (E2 + 3)/4;
    int edge_blocks = (Wtot*32 + 255)/256;

    static int smem_set = 0;
    if (!smem_set) {
        cudaFuncSetAttribute(k_combine_mma, cudaFuncAttributeMaxDynamicSharedMemorySize, SM_TOT);
        smem_set = 1;
    }

    k_zero_prep<<<ZERO_BLOCKS + PREP_BLOCKS, 256>>>(Wn0, Wa0, Wn1, Wa1,
                            Wm0, bm0, ef0, Wm1, bm1, ef1, Wm2, bm2, ef2, Wu, bu);
    k_anode_bt<<<ANODE_BLOCKS + BT_BLOCKS, 256>>>(h);
    k_edge_all<<<edge_blocks, 256>>>(src0, dst0, src1, dst1, src2, dst2, h, E0, E1, E2);
    k_combine_mma<<<(Nn + 63)/64, 256, SM_TOT>>>(h, out);
    k_scan<<<(Nn + 255)/256, 256>>>();
    k_fixup<<<1024, 96>>>(h, bu, out);
}